// round 5
// baseline (speedup 1.0000x reference)
#include <cuda_runtime.h>

#define FULLMASK 0xFFFFFFFFu

// ---- problem constants (B=8, grids 13/26/52, 3 anchors, 80 classes) ----
#define CPI0 507          // 13*13*3 cells per image
#define CPI1 2028
#define CPI2 8112
#define CELLS0 4056       // * 8 images
#define CELLS1 16224
#define CELLS2 64896
#define TOTCELLS 85176

// persistent grid: 4 blocks/SM * 148 SMs = 592, guaranteed co-resident
#define GRID 592
#define B0S 0
#define B0N 28
#define B1S 28
#define B1N 112
#define B2S 140
#define B2N 452           // 28+112+452 = 592, proportional to 1:4:16 data volume

static __constant__ float c_anch[3][3][2] = {
    {{116.f, 90.f}, {156.f, 198.f}, {373.f, 326.f}},   // mask [6,7,8]
    {{ 30.f, 61.f}, { 62.f,  45.f}, { 59.f, 119.f}},   // mask [3,4,5]
    {{ 10.f, 13.f}, { 16.f,  30.f}, { 33.f,  23.f}}};  // mask [0,1,2]

// ---- static device scratch (zero-initialized at module load; self-reset each run) ----
__device__ double       g_part[6][GRID];    // per-block partials: sxy,swh,sconf,scls,sos,cobj
__device__ unsigned int g_nvalid[24];       // [layer*8 + image]
__device__ unsigned int g_cign[3];          // per-layer exact ignore counts
__device__ unsigned int g_bar1, g_bar2;     // grid barrier / completion counters
__device__ float4       g_boxes[TOTCELLS];  // compacted valid true boxes {xmin,ymin,xmax,ymax}

// ---------------- phase 1: flat element sweep over one float4-pair ----------------
// s[0]=sxy s[1]=swh s[2]=sconf s[3]=scls s[4]=sos s[5]=cobj
template<int LAYER, int GW, int CPI, int CELLBASE>
__device__ __forceinline__ void proc4(float4 z4, float4 f4, int cell, int ch,
                                      const float* __restrict__ lp, float* s)
{
    const float gwf = (float)GW;
    const float iw  = gwf * 32.f;
    float zs[4] = {z4.x, z4.y, z4.z, z4.w};
    float fs[4] = {f4.x, f4.y, f4.z, f4.w};
#pragma unroll
    for (int e = 0; e < 4; e++) {
        float z = zs[e], f = fs[e];
        float zm = z;
        if (ch < 2) {                       // xy: z*grid - coord
            int c3 = cell / 3;
            int xy = (ch == 0) ? (c3 % GW) : ((c3 / GW) % GW);
            zm = z * gwf - (float)xy;
        }
        // bce(zm, f) = max(f,0) - f*zm + log1p(exp(-|f|)), MUFU-direct
        float v = fmaxf(f, 0.f) - f * zm + __logf(1.f + __expf(-fabsf(f)));
        if (ch >= 5) {
            s[3] += v;                      // cls
        } else if (ch < 2) {
            s[0] += v;                      // xy
        } else if (ch == 4) {
            s[2] += v;                      // conf
            s[5] += z;                      // cobj (z is obj here)
            if (z != 0.f) {                 // rare (~2%): sos + box compaction
                const float* c = lp + (size_t)cell * 85;
                float lx = c[0], ly = c[1], lw = c[2], lh = c[3];
                s[4] += z * (2.f - lw * lh);
                int b = cell / CPI;
                unsigned slot = atomicAdd(&g_nvalid[LAYER * 8 + b], 1u);
                g_boxes[CELLBASE + b * CPI + (int)slot] =
                    make_float4(lx - lw * 0.5f, ly - lh * 0.5f,
                                lx + lw * 0.5f, ly + lh * 0.5f);
            }
        } else {                            // ch 2 or 3: wh term (only if obj != 0)
            const float* c = lp + (size_t)cell * 85;
            float obj = c[4];
            if (obj != 0.f) {
                float lw = (ch == 2) ? z : c[2];
                float lh = (ch == 3) ? z : c[3];
                int a = cell % 3;
                float anchor = (ch == 2) ? c_anch[LAYER][a][0] : c_anch[LAYER][a][1];
                float t = __logf(z * iw / anchor) - f;
                s[1] += obj * (2.f - lw * lh) * 0.5f * t * t;
            }
        }
        ch++;
        if (ch == 85) { ch = 0; cell++; }
    }
}

template<int LAYER, int GW, int CPI, int CELLS, int CELLBASE, int BSTART, int NBLK>
__device__ __forceinline__ void phase1(const float* __restrict__ op,
                                       const float* __restrict__ lp,
                                       float* s, int bId, int tid)
{
    const int NV4 = CELLS * 85 / 4;          // element count divisible by 4 for all layers
    const int nth = NBLK * 256;
    const float4* __restrict__ z4p = (const float4*)lp;
    const float4* __restrict__ f4p = (const float4*)op;
    int t0 = (bId - BSTART) * 256 + tid;
    for (int i = t0; i < NV4; i += 2 * nth) {
        int j = i + nth;
        // batch all 4 independent 16B loads before any consumption (MLP=4)
        float4 za = z4p[i], fa = f4p[i];
        bool hb = (j < NV4);
        float4 zb, fb;
        if (hb) { zb = z4p[j]; fb = f4p[j]; }
        {
            int idx = i * 4;
            int cell = idx / 85;             // constant-divisor magic mul
            proc4<LAYER, GW, CPI, CELLBASE>(za, fa, cell, idx - cell * 85, lp, s);
        }
        if (hb) {
            int idx = j * 4;
            int cell = idx / 85;
            proc4<LAYER, GW, CPI, CELLBASE>(zb, fb, cell, idx - cell * 85, lp, s);
        }
    }
}

// ---------------- phase 2: per-cell ignore test (division-free, replicates ref's
// inter_maxes = maximum(b1max,b2max) bug) ----------------
template<int LAYER, int GW, int CPI, int CELLBASE>
__device__ __forceinline__ bool cell_hit(const float* __restrict__ op,
                                         const float* __restrict__ lp,
                                         int cell, float* obj_out)
{
    int a  = cell % 3;
    int c3 = cell / 3;
    int x  = c3 % GW;
    int y  = (c3 / GW) % GW;
    int b  = cell / CPI;
    const float* ff = op + (size_t)cell * 85;
    float f0 = ff[0], f1 = ff[1], f2v = ff[2], f3 = ff[3];
    *obj_out = lp[(size_t)cell * 85 + 4];

    const float gwf = (float)GW;
    float aw = c_anch[LAYER][a][0], ah = c_anch[LAYER][a][1];
    // precise expf here: keeps the integer ignore count bit-stable vs reference
    float px = (1.f / (1.f + expf(-f0)) + (float)x) / gwf;
    float py = (1.f / (1.f + expf(-f1)) + (float)y) / gwf;
    float pw = expf(f2v) * aw / (gwf * 32.f);
    float ph = expf(f3)  * ah / (gwf * 32.f);

    float b1x0 = px - pw * 0.5f, b1y0 = py - ph * 0.5f;
    float b1x1 = px + pw * 0.5f, b1y1 = py + ph * 0.5f;
    float a1 = pw * ph;

    int n  = (int)__ldcg(&g_nvalid[LAYER * 8 + b]);
    int e0 = CELLBASE + b * CPI;
    bool hit = false;
#pragma unroll 2
    for (int j = 0; j < n; j++) {
        float4 mm = __ldcg(&g_boxes[e0 + j]);
        float a2  = (mm.z - mm.x) * (mm.w - mm.y);
        float ix0 = fmaxf(b1x0, mm.x);
        float iy0 = fmaxf(b1y0, mm.y);
        float ix1 = fmaxf(b1x1, mm.z);   // reference bug: max of maxes — replicate
        float iy1 = fmaxf(b1y1, mm.w);
        float iww = fmaxf(ix1 - ix0, 0.f);
        float ihh = fmaxf(iy1 - iy0, 0.f);
        float inter = iww * ihh;
        float D = a1 + a2 - inter;
        // iou >= 0.5  <=>  D > 0 && 2*inter >= D
        hit = hit || ((D > 0.f) && (2.f * inter >= D));
    }
    return hit;
}

// ---------------- fused persistent kernel ----------------
__global__ void __launch_bounds__(256, 4) k_fused(
    const float* __restrict__ o0, const float* __restrict__ l0,
    const float* __restrict__ o1, const float* __restrict__ l1,
    const float* __restrict__ o2, const float* __restrict__ l2,
    float* __restrict__ out)
{
    const int bId  = blockIdx.x;
    const int lane = threadIdx.x & 31;
    const int warp = threadIdx.x >> 5;

    // ---- phase 1 ----
    float s[6] = {0.f, 0.f, 0.f, 0.f, 0.f, 0.f};
    if (bId < B1S)      phase1<0, 13, CPI0, CELLS0, 0,             B0S, B0N>(o0, l0, s, bId, threadIdx.x);
    else if (bId < B2S) phase1<1, 26, CPI1, CELLS1, CELLS0,        B1S, B1N>(o1, l1, s, bId, threadIdx.x);
    else                phase1<2, 52, CPI2, CELLS2, CELLS0+CELLS1, B2S, B2N>(o2, l2, s, bId, threadIdx.x);

    __shared__ float sh[6][8];
#pragma unroll
    for (int i = 0; i < 6; i++) {
        float v = s[i];
        for (int off = 16; off; off >>= 1) v += __shfl_down_sync(FULLMASK, v, off);
        if (lane == 0) sh[i][warp] = v;
    }
    __syncthreads();
    if (threadIdx.x < 6) {
        double d = 0.0;
        for (int w = 0; w < 8; w++) d += (double)sh[threadIdx.x][w];
        g_part[threadIdx.x][bId] = d;
    }

    // ---- grid barrier (all 592 blocks co-resident by launch_bounds) ----
    __syncthreads();
    if (threadIdx.x == 0) {
        __threadfence();
        atomicAdd(&g_bar1, 1u);
        while (*(volatile unsigned int*)&g_bar1 < GRID) { }
    }
    __syncthreads();

    // ---- phase 2 ----
    __shared__ unsigned int shc[3];
    __shared__ bool s_last;
    if (threadIdx.x < 3) shc[threadIdx.x] = 0u;
    __syncthreads();

    int idx = bId * 256 + threadIdx.x;
    if (idx < TOTCELLS) {
        float obj; bool hit; int layer;
        if (idx < CELLS0)               { layer = 0; hit = cell_hit<0, 13, CPI0, 0>            (o0, l0, idx, &obj); }
        else if (idx < CELLS0 + CELLS1) { layer = 1; hit = cell_hit<1, 26, CPI1, CELLS0>       (o1, l1, idx - CELLS0, &obj); }
        else                            { layer = 2; hit = cell_hit<2, 52, CPI2, CELLS0+CELLS1>(o2, l2, idx - CELLS0 - CELLS1, &obj); }
        if (obj == 0.f && !hit) atomicAdd(&shc[layer], 1u);
    }
    __syncthreads();
    if (threadIdx.x < 3 && shc[threadIdx.x]) atomicAdd(&g_cign[threadIdx.x], shc[threadIdx.x]);
    __syncthreads();
    if (threadIdx.x == 0) {
        __threadfence();
        unsigned t = atomicAdd(&g_bar2, 1u);
        s_last = (t == (unsigned)(GRID - 1));
    }
    __syncthreads();
    if (!s_last) return;

    // ---- final reduce + combine (exactly one block, after all others finished) ----
    __shared__ double res[3][6];
    for (int task = warp; task < 18; task += 8) {
        int layer = task / 6, val = task - layer * 6;
        int start = (layer == 0) ? B0S : (layer == 1) ? B1S : B2S;
        int cnt   = (layer == 0) ? B0N : (layer == 1) ? B1N : B2N;
        double d = 0.0;
        for (int i = lane; i < cnt; i += 32) d += __ldcg(&g_part[val][start + i]);
        for (int off = 16; off; off >>= 1) d += __shfl_down_sync(FULLMASK, d, off);
        if (lane == 0) res[layer][val] = d;
    }
    __syncthreads();
    if (threadIdx.x == 0) {
        const int cpis[3] = {CPI0, CPI1, CPI2};
        double loss = 0.0;
        for (int l = 0; l < 3; l++) {
            double N     = 8.0 * (double)cpis[l];
            double mxy   = res[l][0] / (N * 2.0);
            double mconf = res[l][2] / N;
            double mcls  = res[l][3] / (N * 80.0);
            unsigned ci  = *(volatile unsigned int*)&g_cign[l];
            loss += mxy * res[l][4]                          // xy_loss * B
                  + res[l][1]                                // wh_loss * B
                  + mconf * (res[l][5] + (double)ci)         // conf_loss * B
                  + mcls * res[l][5];                        // class_loss * B
        }
        *out = (float)(loss / 8.0);
    }
    __syncthreads();
    // self-reset for the next graph replay (initial state is zero-init at load)
    if (threadIdx.x < 24)                       g_nvalid[threadIdx.x] = 0u;
    if (threadIdx.x >= 24 && threadIdx.x < 27)  g_cign[threadIdx.x - 24] = 0u;
    if (threadIdx.x == 30)                      g_bar1 = 0u;
    if (threadIdx.x == 31)                      g_bar2 = 0u;
}

extern "C" void kernel_launch(void* const* d_in, const int* in_sizes, int n_in,
                              void* d_out, int out_size) {
    const float *O[3], *L[3];
    // o_i and l_i have equal element counts per layer; layers differ.
    // interleaved order (o0,l0,o1,l1,o2,l2) <=> sizes[0]==sizes[1].
    if (in_sizes[0] == in_sizes[1]) {
        O[0] = (const float*)d_in[0]; L[0] = (const float*)d_in[1];
        O[1] = (const float*)d_in[2]; L[1] = (const float*)d_in[3];
        O[2] = (const float*)d_in[4]; L[2] = (const float*)d_in[5];
    } else {
        O[0] = (const float*)d_in[0]; O[1] = (const float*)d_in[1]; O[2] = (const float*)d_in[2];
        L[0] = (const float*)d_in[3]; L[1] = (const float*)d_in[4]; L[2] = (const float*)d_in[5];
    }
    k_fused<<<GRID, 256>>>(O[0], L[0], O[1], L[1], O[2], L[2], (float*)d_out);
}

// round 6
// speedup vs baseline: 1.2364x; 1.2364x over previous
#include <cuda_runtime.h>
#include <cstdint>

#define FULLMASK 0xFFFFFFFFu

// ---- problem constants (B=8, grids 13/26/52, 3 anchors, 80 classes) ----
#define CPI0 507          // 13*13*3 cells per image
#define CPI1 2028
#define CPI2 8112
#define CELLS0 4056       // * 8 images
#define CELLS1 16224
#define CELLS2 64896
#define TOTCELLS 85176

// persistent grid: 4 blocks/SM * 148 SMs = 592, guaranteed co-resident
#define GRID 592
#define B0S 0
#define B0N 28
#define B1S 28
#define B1N 112
#define B2S 140
#define B2N 452           // 28+112+452 = 592, proportional to 1:4:16 data volume

static __constant__ float c_anch[3][3][2] = {
    {{116.f, 90.f}, {156.f, 198.f}, {373.f, 326.f}},   // mask [6,7,8]
    {{ 30.f, 61.f}, { 62.f,  45.f}, { 59.f, 119.f}},   // mask [3,4,5]
    {{ 10.f, 13.f}, { 16.f,  30.f}, { 33.f,  23.f}}};  // mask [0,1,2]

// ---- static device scratch (zero-initialized at module load; self-reset each run) ----
__device__ double       g_part[6][GRID];    // per-block partials: sxy,swh,sconf,scls,sos,cobj
__device__ unsigned int g_nvalid[24];       // [layer*8 + image]
__device__ unsigned int g_cign[3];          // per-layer exact ignore counts
__device__ unsigned int g_bar1, g_bar2;     // grid barrier / completion counters
__device__ float4       g_boxes[TOTCELLS];  // compacted valid true boxes {xmin,ymin,xmax,ymax}

__device__ __forceinline__ void cp16(uint32_t s, const void* g) {
    asm volatile("cp.async.cg.shared.global [%0], [%1], 16;" :: "r"(s), "l"(g));
}

// ---------------- phase 1: cp.async double-buffered stream + warp-per-cell from smem ----
// Group = 4 cells = 340 floats per stream = 85 float4. Tile layout per warp:
// [buf(2)][stream(2)][85 float4].  s accumulators: sxy,swh,sconf,scls,sos,cobj.
template<int LAYER, int GW, int CPI, int CELLS, int CELLBASE, int BSTART, int NBLK>
__device__ __forceinline__ void phase1(const float* __restrict__ op,
                                       const float* __restrict__ lp,
                                       float* s, int bId, int lane, float4* tbase)
{
    const int NG     = CELLS / 4;
    const int warp   = threadIdx.x >> 5;
    const int gwarp  = (bId - BSTART) * 8 + warp;
    const int nwarps = NBLK * 8;
    const float gwf  = (float)GW;
    const float iw   = gwf * 32.f;
    const float4* z4 = (const float4*)lp;
    const float4* f4 = (const float4*)op;

    const uint32_t sbase = (uint32_t)__cvta_generic_to_shared(tbase);
    const bool has2 = (lane < 21);

    // lane-static masks
    const float m_xy   = (lane < 2)  ? 1.f : 0.f;
    const float m_conf = (lane == 4) ? 1.f : 0.f;
    const float m_cls0 = (lane > 4)  ? 1.f : 0.f;
    const bool  is_wh  = (lane == 2) || (lane == 3);
    const bool  is_bk  = (lane == 31);

    auto issue = [&](int buf, int g) {
        const float4* zs = z4 + (size_t)g * 85;
        const float4* fs = f4 + (size_t)g * 85;
        uint32_t dz = sbase + (uint32_t)(buf * 170) * 16u;
        uint32_t df = dz + 85u * 16u;
        cp16(dz + lane * 16u,        zs + lane);
        cp16(dz + (lane + 32) * 16u, zs + lane + 32);
        cp16(df + lane * 16u,        fs + lane);
        cp16(df + (lane + 32) * 16u, fs + lane + 32);
        if (has2) {
            cp16(dz + (lane + 64) * 16u, zs + lane + 64);
            cp16(df + (lane + 64) * 16u, fs + lane + 64);
        }
        asm volatile("cp.async.commit_group;");
    };

    int buf = 0;
    if (gwarp < NG) issue(0, gwarp);
    for (int g = gwarp; g < NG; g += nwarps) {
        int gn = g + nwarps;
        if (gn < NG) {
            issue(buf ^ 1, gn);
            asm volatile("cp.async.wait_group 1;");
        } else {
            asm volatile("cp.async.wait_group 0;");
        }
        __syncwarp();

        const float* Z = (const float*)(tbase + buf * 170);
        const float* F = Z + 340;
#pragma unroll
        for (int c = 0; c < 4; c++) {
            int cellg = g * 4 + c;
            float z0 = Z[c * 85 + lane],      f0 = F[c * 85 + lane];
            float z1 = Z[c * 85 + lane + 32], f1 = F[c * 85 + lane + 32];
            float obj = Z[c * 85 + 4];          // uniform -> smem broadcast

            float zm = z0;
            if (lane < 2) {
                int c3 = cellg / 3;             // compile-time divisors -> magic mul
                int xy = (lane == 0) ? (c3 % GW) : ((c3 / GW) % GW);
                zm = z0 * gwf - (float)xy;
            }
            float v0 = fmaxf(f0, 0.f) - f0 * zm + __logf(1.f + __expf(-fabsf(f0)));
            float v1 = fmaxf(f1, 0.f) - f1 * z1 + __logf(1.f + __expf(-fabsf(f1)));
            float v2 = 0.f;
            if (has2) {
                float z2 = Z[c * 85 + lane + 64], f2 = F[c * 85 + lane + 64];
                v2 = fmaxf(f2, 0.f) - f2 * z2 + __logf(1.f + __expf(-fabsf(f2)));
            }
            s[0] += m_xy   * v0;
            s[2] += m_conf * v0;
            s[3] += m_cls0 * v0 + v1 + v2;

            if (is_wh && obj != 0.f) {          // rare (~2%)
                float lw = Z[c * 85 + 2], lh = Z[c * 85 + 3];
                int a = cellg % 3;
                float anchor = c_anch[LAYER][a][lane - 2];
                float t = __logf(z0 * iw / anchor) - f0;
                s[1] += obj * (2.f - lw * lh) * 0.5f * t * t;
            }
            if (is_bk) {
                s[5] += obj;
                if (obj != 0.f) {               // rare: sos + box compaction
                    float lx = Z[c * 85 + 0], ly = Z[c * 85 + 1];
                    float lw = Z[c * 85 + 2], lh = Z[c * 85 + 3];
                    s[4] += obj * (2.f - lw * lh);
                    int b = cellg / CPI;
                    unsigned slot = atomicAdd(&g_nvalid[LAYER * 8 + b], 1u);
                    g_boxes[CELLBASE + b * CPI + (int)slot] =
                        make_float4(lx - lw * 0.5f, ly - lh * 0.5f,
                                    lx + lw * 0.5f, ly + lh * 0.5f);
                }
            }
        }
        buf ^= 1;
        __syncwarp();     // all lanes done with this buffer before it is refilled
    }
}

// ---------------- phase 2: per-cell ignore test (division-free, replicates ref's
// inter_maxes = maximum(b1max,b2max) bug). Plain loads: boxes L1-cacheable (first
// read happens after the fence+grid barrier; no stale lines possible). ----------------
template<int LAYER, int GW, int CPI, int CELLBASE>
__device__ __forceinline__ bool cell_hit(const float* __restrict__ op,
                                         const float* __restrict__ lp,
                                         int cell, float* obj_out)
{
    int a  = cell % 3;
    int c3 = cell / 3;
    int x  = c3 % GW;
    int y  = (c3 / GW) % GW;
    int b  = cell / CPI;
    const float* ff = op + (size_t)cell * 85;
    float f0 = ff[0], f1 = ff[1], f2v = ff[2], f3 = ff[3];
    *obj_out = lp[(size_t)cell * 85 + 4];

    const float gwf = (float)GW;
    float aw = c_anch[LAYER][a][0], ah = c_anch[LAYER][a][1];
    // precise expf here: keeps the integer ignore count bit-stable vs reference
    float px = (1.f / (1.f + expf(-f0)) + (float)x) / gwf;
    float py = (1.f / (1.f + expf(-f1)) + (float)y) / gwf;
    float pw = expf(f2v) * aw / (gwf * 32.f);
    float ph = expf(f3)  * ah / (gwf * 32.f);

    float b1x0 = px - pw * 0.5f, b1y0 = py - ph * 0.5f;
    float b1x1 = px + pw * 0.5f, b1y1 = py + ph * 0.5f;
    float a1 = pw * ph;

    auto tst = [&](float4 mm) -> bool {
        float a2  = (mm.z - mm.x) * (mm.w - mm.y);
        float ix0 = fmaxf(b1x0, mm.x);
        float iy0 = fmaxf(b1y0, mm.y);
        float ix1 = fmaxf(b1x1, mm.z);   // reference bug: max of maxes — replicate
        float iy1 = fmaxf(b1y1, mm.w);
        float inter = fmaxf(ix1 - ix0, 0.f) * fmaxf(iy1 - iy0, 0.f);
        float D = a1 + a2 - inter;
        return (D > 0.f) && (2.f * inter >= D);   // <=> iou >= 0.5
    };

    int n  = (int)__ldcg(&g_nvalid[LAYER * 8 + b]);
    int e0 = CELLBASE + b * CPI;
    bool hit = false;
    int j = 0;
    for (; j + 4 <= n; j += 4) {       // batched loads -> MLP 4, L1-resident
        float4 m0 = g_boxes[e0 + j],     m1 = g_boxes[e0 + j + 1];
        float4 m2 = g_boxes[e0 + j + 2], m3 = g_boxes[e0 + j + 3];
        hit = hit | tst(m0) | tst(m1) | tst(m2) | tst(m3);
    }
    for (; j < n; j++) hit = hit | tst(g_boxes[e0 + j]);
    return hit;
}

// ---------------- fused persistent kernel ----------------
__global__ void __launch_bounds__(256, 4) k_fused(
    const float* __restrict__ o0, const float* __restrict__ l0,
    const float* __restrict__ o1, const float* __restrict__ l1,
    const float* __restrict__ o2, const float* __restrict__ l2,
    float* __restrict__ out)
{
    __shared__ float4 s_tile[8][2 * 170];      // [warp][buf*170 + stream*85 + i] = 43.5KB
    const int bId  = blockIdx.x;
    const int lane = threadIdx.x & 31;
    const int warp = threadIdx.x >> 5;

    // ---- phase 1 ----
    float s[6] = {0.f, 0.f, 0.f, 0.f, 0.f, 0.f};
    if (bId < B1S)      phase1<0, 13, CPI0, CELLS0, 0,             B0S, B0N>(o0, l0, s, bId, lane, s_tile[warp]);
    else if (bId < B2S) phase1<1, 26, CPI1, CELLS1, CELLS0,        B1S, B1N>(o1, l1, s, bId, lane, s_tile[warp]);
    else                phase1<2, 52, CPI2, CELLS2, CELLS0+CELLS1, B2S, B2N>(o2, l2, s, bId, lane, s_tile[warp]);

    __shared__ float sh[6][8];
#pragma unroll
    for (int i = 0; i < 6; i++) {
        float v = s[i];
        for (int off = 16; off; off >>= 1) v += __shfl_down_sync(FULLMASK, v, off);
        if (lane == 0) sh[i][warp] = v;
    }
    __syncthreads();
    if (threadIdx.x < 6) {
        double d = 0.0;
        for (int w = 0; w < 8; w++) d += (double)sh[threadIdx.x][w];
        g_part[threadIdx.x][bId] = d;
    }

    // ---- grid barrier (all 592 blocks co-resident by launch_bounds) ----
    __syncthreads();
    if (threadIdx.x == 0) {
        __threadfence();
        atomicAdd(&g_bar1, 1u);
        while (*(volatile unsigned int*)&g_bar1 < GRID) { }
    }
    __syncthreads();

    // ---- phase 2 ----
    __shared__ unsigned int shc[3];
    __shared__ bool s_last;
    if (threadIdx.x < 3) shc[threadIdx.x] = 0u;
    __syncthreads();

    int idx = bId * 256 + threadIdx.x;
    if (idx < TOTCELLS) {
        float obj; bool hit; int layer;
        if (idx < CELLS0)               { layer = 0; hit = cell_hit<0, 13, CPI0, 0>            (o0, l0, idx, &obj); }
        else if (idx < CELLS0 + CELLS1) { layer = 1; hit = cell_hit<1, 26, CPI1, CELLS0>       (o1, l1, idx - CELLS0, &obj); }
        else                            { layer = 2; hit = cell_hit<2, 52, CPI2, CELLS0+CELLS1>(o2, l2, idx - CELLS0 - CELLS1, &obj); }
        if (obj == 0.f && !hit) atomicAdd(&shc[layer], 1u);
    }
    __syncthreads();
    if (threadIdx.x < 3 && shc[threadIdx.x]) atomicAdd(&g_cign[threadIdx.x], shc[threadIdx.x]);
    __syncthreads();
    if (threadIdx.x == 0) {
        __threadfence();
        unsigned t = atomicAdd(&g_bar2, 1u);
        s_last = (t == (unsigned)(GRID - 1));
    }
    __syncthreads();
    if (!s_last) return;

    // ---- final reduce + combine (exactly one block, after all others finished) ----
    __shared__ double res[3][6];
    for (int task = warp; task < 18; task += 8) {
        int layer = task / 6, val = task - layer * 6;
        int start = (layer == 0) ? B0S : (layer == 1) ? B1S : B2S;
        int cnt   = (layer == 0) ? B0N : (layer == 1) ? B1N : B2N;
        double d = 0.0;
        for (int i = lane; i < cnt; i += 32) d += __ldcg(&g_part[val][start + i]);
        for (int off = 16; off; off >>= 1) d += __shfl_down_sync(FULLMASK, d, off);
        if (lane == 0) res[layer][val] = d;
    }
    __syncthreads();
    if (threadIdx.x == 0) {
        const int cpis[3] = {CPI0, CPI1, CPI2};
        double loss = 0.0;
        for (int l = 0; l < 3; l++) {
            double N     = 8.0 * (double)cpis[l];
            double mxy   = res[l][0] / (N * 2.0);
            double mconf = res[l][2] / N;
            double mcls  = res[l][3] / (N * 80.0);
            unsigned ci  = *(volatile unsigned int*)&g_cign[l];
            loss += mxy * res[l][4]                          // xy_loss * B
                  + res[l][1]                                // wh_loss * B
                  + mconf * (res[l][5] + (double)ci)         // conf_loss * B
                  + mcls * res[l][5];                        // class_loss * B
        }
        *out = (float)(loss / 8.0);
    }
    __syncthreads();
    // self-reset for the next graph replay (initial state is zero-init at load)
    if (threadIdx.x < 24)                       g_nvalid[threadIdx.x] = 0u;
    if (threadIdx.x >= 24 && threadIdx.x < 27)  g_cign[threadIdx.x - 24] = 0u;
    if (threadIdx.x == 30)                      g_bar1 = 0u;
    if (threadIdx.x == 31)                      g_bar2 = 0u;
}

extern "C" void kernel_launch(void* const* d_in, const int* in_sizes, int n_in,
                              void* d_out, int out_size) {
    const float *O[3], *L[3];
    // o_i and l_i have equal element counts per layer; layers differ.
    // interleaved order (o0,l0,o1,l1,o2,l2) <=> sizes[0]==sizes[1].
    if (in_sizes[0] == in_sizes[1]) {
        O[0] = (const float*)d_in[0]; L[0] = (const float*)d_in[1];
        O[1] = (const float*)d_in[2]; L[1] = (const float*)d_in[3];
        O[2] = (const float*)d_in[4]; L[2] = (const float*)d_in[5];
    } else {
        O[0] = (const float*)d_in[0]; O[1] = (const float*)d_in[1]; O[2] = (const float*)d_in[2];
        L[0] = (const float*)d_in[3]; L[1] = (const float*)d_in[4]; L[2] = (const float*)d_in[5];
    }
    k_fused<<<GRID, 256>>>(O[0], L[0], O[1], L[1], O[2], L[2], (float*)d_out);
}

// round 7
// speedup vs baseline: 1.5208x; 1.2301x over previous
#include <cuda_runtime.h>
#include <cstdint>

#define FULLMASK 0xFFFFFFFFu

// ---- problem constants (B=8, grids 13/26/52, 3 anchors, 80 classes) ----
#define CPI0 507          // 13*13*3 cells per image
#define CPI1 2028
#define CPI2 8112
#define CELLS0 4056       // * 8 images
#define CELLS1 16224
#define CELLS2 64896
#define TOTCELLS 85176
#define C01    (CELLS0 + CELLS1)      // 20280

// persistent grid: 4 blocks/SM * 148 SMs = 592, guaranteed co-resident
#define GRID 592
#define B0S 0
#define B0N 28
#define B1S 28
#define B1N 112
#define B2S 140
#define B2N 452           // 28+112+452 = 592, proportional to 1:4:16 data volume

static __constant__ float c_anch[3][3][2] = {
    {{116.f, 90.f}, {156.f, 198.f}, {373.f, 326.f}},   // mask [6,7,8]
    {{ 30.f, 61.f}, { 62.f,  45.f}, { 59.f, 119.f}},   // mask [3,4,5]
    {{ 10.f, 13.f}, { 16.f,  30.f}, { 33.f,  23.f}}};  // mask [0,1,2]

// ---- static device scratch (zero-initialized at module load; self-reset each run) ----
__device__ double       g_part[6][GRID];    // per-block partials: sxy,swh,sconf,scls,sos,cobj
__device__ unsigned int g_nvalid[24];       // [layer*8 + image]
__device__ unsigned int g_cign[3];          // per-layer exact ignore counts
__device__ unsigned int g_bar1, g_bar2;     // grid barrier / completion counters
__device__ float4       g_boxes[TOTCELLS];  // compacted valid true boxes {xmin,ymin,xmax,ymax}

__device__ __forceinline__ void cp16(uint32_t s, const void* g) {
    asm volatile("cp.async.cg.shared.global [%0], [%1], 16;" :: "r"(s), "l"(g));
}
__device__ __forceinline__ float bcef(float z, float x) {
    // max(x,0) - x*z + log1p(exp(-|x|)), MUFU-direct
    return fmaxf(x, 0.f) - x * z + __logf(1.f + __expf(-fabsf(x)));
}
__device__ __forceinline__ float bce4(float4 z, float4 f) {
    return bcef(z.x, f.x) + bcef(z.y, f.y) + bcef(z.z, f.z) + bcef(z.w, f.w);
}

// ---------------- phase 1: cp.async stream + branch-free uniform sum + correction ----
// Group = 4 cells = 340 floats per stream (85 float4, 16B-aligned per group).
// Tile per warp: [buf(2)][z(85 f4) | f(85 f4)].
template<int LAYER, int GW, int CPI, int CELLS, int CELLBASE, int BSTART, int NBLK>
__device__ __forceinline__ void phase1(const float* __restrict__ op,
                                       const float* __restrict__ lp,
                                       float* s, int bId, int lane, float4* tbase)
{
    const int NG     = CELLS / 4;
    const int warp   = threadIdx.x >> 5;
    const int gwarp  = (bId - BSTART) * 8 + warp;
    const int nwarps = NBLK * 8;
    const float iwf  = (float)GW * 32.f;
    const float4* z4 = (const float4*)lp;
    const float4* f4 = (const float4*)op;
    const uint32_t sbase = (uint32_t)__cvta_generic_to_shared(tbase);

    // ---- lane constants ----
    const bool  has2 = (lane < 21);
    const float m2   = has2 ? 1.f : 0.f;
    const int   sl2  = has2 ? lane + 64 : lane;        // safe fallback address
    const bool  sp   = (lane < 20);                    // special lanes: (cell myc, ch myk)
    const int   myc  = sp ? (lane / 5) : 0;
    const int   myk  = sp ? (lane % 5) : 0;
    const float m_sp  = sp ? 1.f : 0.f;
    const float m_k01 = (sp && myk < 2) ? 1.f : 0.f;
    const float m_k4  = (sp && myk == 4) ? 1.f : 0.f;
    const bool  is_k4 = (sp && myk == 4);
    const float m_k23 = (sp && (myk == 2 || myk == 3)) ? 1.f : 0.f;
    const int   off_k  = myc * 85 + myk;
    const int   off_lw = myc * 85 + 2;
    const int   off_lh = myc * 85 + 3;
    const int   off_ob = myc * 85 + 4;
    const int   anch_sel = (myk == 3) ? 1 : 0;

    auto issue = [&](int buf, int g) {
        const float4* zs = z4 + (size_t)g * 85;
        const float4* fs = f4 + (size_t)g * 85;
        uint32_t dz = sbase + (uint32_t)(buf * 170) * 16u;
        uint32_t df = dz + 85u * 16u;
        cp16(dz + lane * 16u,        zs + lane);
        cp16(dz + (lane + 32) * 16u, zs + lane + 32);
        cp16(df + lane * 16u,        fs + lane);
        cp16(df + (lane + 32) * 16u, fs + lane + 32);
        if (has2) {
            cp16(dz + (lane + 64) * 16u, zs + lane + 64);
            cp16(df + (lane + 64) * 16u, fs + lane + 64);
        }
        asm volatile("cp.async.commit_group;");
    };

    int buf = 0;
    if (gwarp < NG) issue(0, gwarp);
    for (int g = gwarp; g < NG; g += nwarps) {
        int gn = g + nwarps;
        if (gn < NG) {
            issue(buf ^ 1, gn);
            asm volatile("cp.async.wait_group 1;");
        } else {
            asm volatile("cp.async.wait_group 0;");
        }
        __syncwarp();

        const float*  Z  = (const float*)(tbase + buf * 170);
        const float*  F  = Z + 340;
        const float4* Zv = (const float4*)Z;
        const float4* Fv = (const float4*)F;

        // ---- uniform: plain bce over ALL 340 elements (no masks, no branches) ----
        float4 za = Zv[lane],      fa = Fv[lane];
        float4 zb = Zv[lane + 32], fb = Fv[lane + 32];
        float4 zc = Zv[sl2],       fc = Fv[sl2];
        s[3] += bce4(za, fa) + bce4(zb, fb) + m2 * bce4(zc, fc);

        // ---- per-lane cell coordinates (compile-time divisors) ----
        int cellg = g * 4 + myc;
        int c3 = cellg / 3;
        int a  = cellg - 3 * c3;
        int x  = c3 % GW;
        int y  = (c3 / GW) % GW;

        // ---- special correction (lanes 0-19, fully predicated) ----
        float zk   = Z[off_k],  fk  = F[off_k];
        float objc = Z[off_ob];
        float lwv  = Z[off_lw], lhv = Z[off_lh];
        float vsp  = bcef(zk, fk);

        s[3] -= m_sp * vsp;                                       // remove non-cls chans
        float coordf = (myk == 0) ? (float)x : (float)y;
        // bce(z*GW - coord, f) = bce(z,f) + f*z*(1-GW) + coord*f
        s[0] += m_k01 * (vsp + (1.f - (float)GW) * fk * zk + coordf * fk);
        s[2] += m_k4 * vsp;

        float anch = c_anch[LAYER][a][anch_sel];
        float t    = __logf(__fdividef(fmaxf(zk, 1e-30f) * iwf, anch)) - fk;
        float sc23 = m_k23 * objc * (2.f - lwv * lhv) * 0.5f;     // 0 unless wh lane & obj
        s[1] += sc23 * t * t;
        s[5] += m_k4 * objc;
        s[4] += m_k4 * objc * (2.f - lwv * lhv);

        // ---- rare box compaction (warp-uniform ballot guard) ----
        bool want = is_k4 && (objc != 0.f);
        if (__ballot_sync(FULLMASK, want)) {
            if (want) {
                float lx = Z[myc * 85 + 0], ly = Z[myc * 85 + 1];
                int bimg = cellg / CPI;
                unsigned slot = atomicAdd(&g_nvalid[LAYER * 8 + bimg], 1u);
                g_boxes[CELLBASE + bimg * CPI + (int)slot] =
                    make_float4(lx - lwv * 0.5f, ly - lhv * 0.5f,
                                lx + lwv * 0.5f, ly + lhv * 0.5f);
            }
        }
        buf ^= 1;
        __syncwarp();     // buffer fully consumed before refill
    }
}

// ---------------- phase 2: ignore test, (start, step) strided over the box list.
// Replicates the reference's inter_maxes = maximum(b1max, b2max) bug. ----------------
template<int LAYER, int GW, int CPI, int CELLBASE>
__device__ __forceinline__ bool cell_hit(const float* __restrict__ op,
                                         const float* __restrict__ lp,
                                         int cell, int start, int step,
                                         float* obj_out)
{
    int a  = cell % 3;
    int c3 = cell / 3;
    int x  = c3 % GW;
    int y  = (c3 / GW) % GW;
    int b  = cell / CPI;
    const float* ff = op + (size_t)cell * 85;
    float f0 = ff[0], f1 = ff[1], f2v = ff[2], f3 = ff[3];
    *obj_out = lp[(size_t)cell * 85 + 4];

    const float gwf = (float)GW;
    float aw = c_anch[LAYER][a][0], ah = c_anch[LAYER][a][1];
    // precise expf here: keeps the integer ignore count bit-stable vs reference
    float px = (1.f / (1.f + expf(-f0)) + (float)x) / gwf;
    float py = (1.f / (1.f + expf(-f1)) + (float)y) / gwf;
    float pw = expf(f2v) * aw / (gwf * 32.f);
    float ph = expf(f3)  * ah / (gwf * 32.f);

    float b1x0 = px - pw * 0.5f, b1y0 = py - ph * 0.5f;
    float b1x1 = px + pw * 0.5f, b1y1 = py + ph * 0.5f;
    float a1 = pw * ph;

    auto tst = [&](float4 mm) -> bool {
        float a2  = (mm.z - mm.x) * (mm.w - mm.y);
        float ix0 = fmaxf(b1x0, mm.x);
        float iy0 = fmaxf(b1y0, mm.y);
        float ix1 = fmaxf(b1x1, mm.z);   // reference bug: max of maxes — replicate
        float iy1 = fmaxf(b1y1, mm.w);
        float inter = fmaxf(ix1 - ix0, 0.f) * fmaxf(iy1 - iy0, 0.f);
        float D = a1 + a2 - inter;
        return (D > 0.f) && (2.f * inter >= D);   // <=> iou >= 0.5
    };

    int n  = (int)__ldcg(&g_nvalid[LAYER * 8 + b]);
    int e0 = CELLBASE + b * CPI;
    bool hit = false;
    int j = start;
    for (; j + 3 * step < n; j += 4 * step) {     // batched -> MLP 4, L2-resident
        float4 m0 = g_boxes[e0 + j];
        float4 m1 = g_boxes[e0 + j + step];
        float4 m2v = g_boxes[e0 + j + 2 * step];
        float4 m3 = g_boxes[e0 + j + 3 * step];
        hit = hit | tst(m0) | tst(m1) | tst(m2v) | tst(m3);
    }
    for (; j < n; j += step) hit = hit | tst(g_boxes[e0 + j]);
    return hit;
}

// ---------------- fused persistent kernel ----------------
__global__ void __launch_bounds__(256, 4) k_fused(
    const float* __restrict__ o0, const float* __restrict__ l0,
    const float* __restrict__ o1, const float* __restrict__ l1,
    const float* __restrict__ o2, const float* __restrict__ l2,
    float* __restrict__ out)
{
    __shared__ float4 s_tile[8][2 * 170];      // [warp][buf*170 + i] = 43.5KB
    const int bId  = blockIdx.x;
    const int lane = threadIdx.x & 31;
    const int warp = threadIdx.x >> 5;

    // ---- phase 1 ----
    float s[6] = {0.f, 0.f, 0.f, 0.f, 0.f, 0.f};
    if (bId < B1S)      phase1<0, 13, CPI0, CELLS0, 0,      B0S, B0N>(o0, l0, s, bId, lane, s_tile[warp]);
    else if (bId < B2S) phase1<1, 26, CPI1, CELLS1, CELLS0, B1S, B1N>(o1, l1, s, bId, lane, s_tile[warp]);
    else                phase1<2, 52, CPI2, CELLS2, C01,    B2S, B2N>(o2, l2, s, bId, lane, s_tile[warp]);

    __shared__ float sh[6][8];
#pragma unroll
    for (int i = 0; i < 6; i++) {
        float v = s[i];
        for (int off = 16; off; off >>= 1) v += __shfl_down_sync(FULLMASK, v, off);
        if (lane == 0) sh[i][warp] = v;
    }
    __syncthreads();
    if (threadIdx.x < 6) {
        double d = 0.0;
        for (int w = 0; w < 8; w++) d += (double)sh[threadIdx.x][w];
        g_part[threadIdx.x][bId] = d;
    }

    // ---- grid barrier (all 592 blocks co-resident by launch_bounds) ----
    __syncthreads();
    if (threadIdx.x == 0) {
        __threadfence();
        atomicAdd(&g_bar1, 1u);
        while (*(volatile unsigned int*)&g_bar1 < GRID) { }
    }
    __syncthreads();

    // ---- phase 2 (layer-2 cells split 2 threads/cell) ----
    __shared__ unsigned int shc[3];
    __shared__ bool s_last;
    if (threadIdx.x < 3) shc[threadIdx.x] = 0u;
    __syncthreads();

    int gtid = bId * 256 + threadIdx.x;
    float obj = 1.f;           // dummy: never counts
    bool  hit = false;
    int   layer = 0;
    bool  valid = false, split = false, counter = false;
    if (gtid < CELLS0) {
        valid = true; counter = true; layer = 0;
        hit = cell_hit<0, 13, CPI0, 0>(o0, l0, gtid, 0, 1, &obj);
    } else if (gtid < C01) {
        valid = true; counter = true; layer = 1;
        hit = cell_hit<1, 26, CPI1, CELLS0>(o1, l1, gtid - CELLS0, 0, 1, &obj);
    } else {
        int u = gtid - C01;
        if (u < 2 * CELLS2) {
            valid = true; split = true; layer = 2;
            int cell = u >> 1, half = u & 1;
            counter = (half == 0);
            hit = cell_hit<2, 52, CPI2, C01>(o2, l2, cell, half, 2, &obj);
        }
    }
    // unconditional pair-combine (all lanes participate; non-split lanes discard)
    int h  = hit ? 1 : 0;
    int hx = __shfl_xor_sync(FULLMASK, h, 1);
    bool hitc = split ? ((h | hx) != 0) : hit;
    if (valid && counter && obj == 0.f && !hitc)
        atomicAdd(&shc[layer], 1u);

    __syncthreads();
    if (threadIdx.x < 3 && shc[threadIdx.x]) atomicAdd(&g_cign[threadIdx.x], shc[threadIdx.x]);
    __syncthreads();
    if (threadIdx.x == 0) {
        __threadfence();
        unsigned t = atomicAdd(&g_bar2, 1u);
        s_last = (t == (unsigned)(GRID - 1));
    }
    __syncthreads();
    if (!s_last) return;

    // ---- final reduce + combine (exactly one block, after all others finished) ----
    __shared__ double res[3][6];
    for (int task = warp; task < 18; task += 8) {
        int layr = task / 6, val = task - layr * 6;
        int start = (layr == 0) ? B0S : (layr == 1) ? B1S : B2S;
        int cnt   = (layr == 0) ? B0N : (layr == 1) ? B1N : B2N;
        double d = 0.0;
        for (int i = lane; i < cnt; i += 32) d += __ldcg(&g_part[val][start + i]);
        for (int off = 16; off; off >>= 1) d += __shfl_down_sync(FULLMASK, d, off);
        if (lane == 0) res[layr][val] = d;
    }
    __syncthreads();
    if (threadIdx.x == 0) {
        const int cpis[3] = {CPI0, CPI1, CPI2};
        double loss = 0.0;
        for (int l = 0; l < 3; l++) {
            double N     = 8.0 * (double)cpis[l];
            double mxy   = res[l][0] / (N * 2.0);
            double mconf = res[l][2] / N;
            double mcls  = res[l][3] / (N * 80.0);
            unsigned ci  = *(volatile unsigned int*)&g_cign[l];
            loss += mxy * res[l][4]                          // xy_loss * B
                  + res[l][1]                                // wh_loss * B
                  + mconf * (res[l][5] + (double)ci)         // conf_loss * B
                  + mcls * res[l][5];                        // class_loss * B
        }
        *out = (float)(loss / 8.0);
    }
    __syncthreads();
    // self-reset for the next graph replay (initial state is zero-init at load)
    if (threadIdx.x < 24)                       g_nvalid[threadIdx.x] = 0u;
    if (threadIdx.x >= 24 && threadIdx.x < 27)  g_cign[threadIdx.x - 24] = 0u;
    if (threadIdx.x == 30)                      g_bar1 = 0u;
    if (threadIdx.x == 31)                      g_bar2 = 0u;
}

extern "C" void kernel_launch(void* const* d_in, const int* in_sizes, int n_in,
                              void* d_out, int out_size) {
    const float *O[3], *L[3];
    // o_i and l_i have equal element counts per layer; layers differ.
    // interleaved order (o0,l0,o1,l1,o2,l2) <=> sizes[0]==sizes[1].
    if (in_sizes[0] == in_sizes[1]) {
        O[0] = (const float*)d_in[0]; L[0] = (const float*)d_in[1];
        O[1] = (const float*)d_in[2]; L[1] = (const float*)d_in[3];
        O[2] = (const float*)d_in[4]; L[2] = (const float*)d_in[5];
    } else {
        O[0] = (const float*)d_in[0]; O[1] = (const float*)d_in[1]; O[2] = (const float*)d_in[2];
        L[0] = (const float*)d_in[3]; L[1] = (const float*)d_in[4]; L[2] = (const float*)d_in[5];
    }
    k_fused<<<GRID, 256>>>(O[0], L[0], O[1], L[1], O[2], L[2], (float*)d_out);
}

// round 8
// speedup vs baseline: 1.6036x; 1.0544x over previous
#include <cuda_runtime.h>
#include <cstdint>

#define FULLMASK 0xFFFFFFFFu
#define LN2 0.693147180559945309

// ---- problem constants (B=8, grids 13/26/52, 3 anchors, 80 classes) ----
#define CPI0 507          // 13*13*3 cells per image
#define CPI1 2028
#define CPI2 8112
#define CELLS0 4056       // * 8 images
#define CELLS1 16224
#define CELLS2 64896
#define TOTCELLS 85176
#define C01    20280      // CELLS0 + CELLS1
#define NV4_0  86190      // CELLS0*85/4
#define NV4_1  344760
#define NV4_2  1379040

// persistent grid: 2 blocks/SM * 148 SMs = 296 x 512 threads, guaranteed co-resident
#define GRID 296
#define NTH  512
// pass-A (uniform stream) block ranges per layer, ~1:4:16
#define A0S 0
#define A0N 14
#define A1S 14
#define A1N 56
#define A2S 70
#define A2N 226
// pass-B (per-cell correction) block ranges (block-aligned per layer)
#define BB0S 0
#define BB0N 8            // 8*512 >= 4056
#define BB1S 8
#define BB1N 32           // 32*512 >= 16224
#define BB2S 40
#define BB2N 127          // 127*512 >= 64896

static __constant__ float c_anch[3][3][2] = {
    {{116.f, 90.f}, {156.f, 198.f}, {373.f, 326.f}},   // mask [6,7,8]
    {{ 30.f, 61.f}, { 62.f,  45.f}, { 59.f, 119.f}},   // mask [3,4,5]
    {{ 10.f, 13.f}, { 16.f,  30.f}, { 33.f,  23.f}}};  // mask [0,1,2]

// ---- static device scratch (zero-initialized at module load; self-reset each run) ----
// slots: 0=S_lg 1=S_fz (pass-A layer tag), 2=scorr 3=sxy 4=swh 5=sconf 6=sos 7=cobj (pass-B tag)
__device__ double       g_part[8][GRID];
__device__ unsigned int g_nvalid[24];       // [layer*8 + image]
__device__ unsigned int g_cign[3];          // per-layer exact ignore counts
__device__ unsigned int g_bar1, g_bar2;     // grid barrier / completion counters
__device__ float4       g_boxes[TOTCELLS];  // compacted valid true boxes {xmin,ymin,xmax,ymax}

// ---------------- pass A: structure-free stream ----------------
// bce(z,f) = softplus(f) - f*z  (exact identity).  Sum splits into:
//   S_lg = sum log2(1+exp(f))   (scaled by ln2 at the end)
//   S_fz = sum f*z
__device__ __forceinline__ void accel(float z, float f, float& slg, float& sfz) {
    slg += __log2f(1.f + __expf(f));     // MUFU ex2 + MUFU lg2
    sfz += f * z;
}
__device__ __forceinline__ void acc4(float4 z, float4 f, float& slg, float& sfz) {
    accel(z.x, f.x, slg, sfz); accel(z.y, f.y, slg, sfz);
    accel(z.z, f.z, slg, sfz); accel(z.w, f.w, slg, sfz);
}

template<int NBLK, int BSTART>
__device__ __forceinline__ void sweep(const float* __restrict__ lp,
                                      const float* __restrict__ op,
                                      int NV4, float* s, int bId)
{
    const int nth = NBLK * NTH;
    const float4* __restrict__ z4 = (const float4*)lp;
    const float4* __restrict__ f4 = (const float4*)op;
    float slg = 0.f, sfz = 0.f;
    int i = (bId - BSTART) * NTH + threadIdx.x;
    for (; i + nth < NV4; i += 2 * nth) {
        // 4 independent LDG.128 batched before use (MLP=4/thread)
        float4 za = z4[i], zb = z4[i + nth];
        float4 fa = f4[i], fb = f4[i + nth];
        acc4(za, fa, slg, sfz);
        acc4(zb, fb, slg, sfz);
    }
    if (i < NV4) { float4 z = z4[i], f = f4[i]; acc4(z, f, slg, sfz); }
    s[0] += slg;
    s[1] += sfz;
}

// ---------------- pass B: per-cell correction (1 thread/cell) ----------------
template<int LAYER, int GW, int CPI, int CELLBASE>
__device__ __forceinline__ void correct(const float* __restrict__ op,
                                        const float* __restrict__ lp,
                                        int cell, float* s)
{
    const float* zz = lp + (size_t)cell * 85;
    const float* ff = op + (size_t)cell * 85;
    float z0 = zz[0], z1 = zz[1], z2 = zz[2], z3 = zz[3], z4v = zz[4];
    float f0 = ff[0], f1 = ff[1], f2 = ff[2], f3 = ff[3], f4v = ff[4];

    float b0 = __log2f(1.f + __expf(f0)) * 0.693147181f - f0 * z0;
    float b1 = __log2f(1.f + __expf(f1)) * 0.693147181f - f1 * z1;
    float b2 = __log2f(1.f + __expf(f2)) * 0.693147181f - f2 * z2;
    float b3 = __log2f(1.f + __expf(f3)) * 0.693147181f - f3 * z3;
    float b4 = __log2f(1.f + __expf(f4v)) * 0.693147181f - f4v * z4v;

    s[2] += b0 + b1 + b2 + b3 + b4;          // remove chans 0-4 from cls sum

    int c3 = cell / 3;                        // compile-time divisors
    int a  = cell - 3 * c3;
    int x  = c3 % GW;
    int y  = (c3 / GW) % GW;

    // bce(z*GW - coord, f) = bce(z,f) + f*z*(1-GW) + coord*f
    const float gm1 = 1.f - (float)GW;
    s[3] += b0 + gm1 * f0 * z0 + (float)x * f0
          + b1 + gm1 * f1 * z1 + (float)y * f1;
    s[5] += b4;
    float obj = z4v;
    s[7] += obj;
    if (obj != 0.f) {                         // rare (~2%)
        float scale = 2.f - z2 * z3;
        s[6] += obj * scale;
        const float iwf = (float)GW * 32.f;
        float t2 = __logf(z2 * iwf / c_anch[LAYER][a][0]) - f2;
        float t3 = __logf(z3 * iwf / c_anch[LAYER][a][1]) - f3;
        s[4] += obj * scale * 0.5f * (t2 * t2 + t3 * t3);
        int b = cell / CPI;
        unsigned slot = atomicAdd(&g_nvalid[LAYER * 8 + b], 1u);
        g_boxes[CELLBASE + b * CPI + (int)slot] =
            make_float4(z0 - z2 * 0.5f, z1 - z3 * 0.5f,
                        z0 + z2 * 0.5f, z1 + z3 * 0.5f);
    }
}

// ---------------- phase 2: ignore test, (start, step) strided over the box list.
// Replicates the reference's inter_maxes = maximum(b1max, b2max) bug. ----------------
template<int LAYER, int GW, int CPI, int CELLBASE>
__device__ __forceinline__ bool cell_hit(const float* __restrict__ op,
                                         const float* __restrict__ lp,
                                         int cell, int start, int step,
                                         float* obj_out)
{
    int a  = cell % 3;
    int c3 = cell / 3;
    int x  = c3 % GW;
    int y  = (c3 / GW) % GW;
    int b  = cell / CPI;
    const float* ff = op + (size_t)cell * 85;
    float f0 = ff[0], f1 = ff[1], f2v = ff[2], f3 = ff[3];
    *obj_out = lp[(size_t)cell * 85 + 4];

    const float gwf = (float)GW;
    float aw = c_anch[LAYER][a][0], ah = c_anch[LAYER][a][1];
    // precise expf here: keeps the integer ignore count bit-stable vs reference
    float px = (1.f / (1.f + expf(-f0)) + (float)x) / gwf;
    float py = (1.f / (1.f + expf(-f1)) + (float)y) / gwf;
    float pw = expf(f2v) * aw / (gwf * 32.f);
    float ph = expf(f3)  * ah / (gwf * 32.f);

    float b1x0 = px - pw * 0.5f, b1y0 = py - ph * 0.5f;
    float b1x1 = px + pw * 0.5f, b1y1 = py + ph * 0.5f;
    float a1 = pw * ph;

    auto tst = [&](float4 mm) -> bool {
        float a2  = (mm.z - mm.x) * (mm.w - mm.y);
        float ix0 = fmaxf(b1x0, mm.x);
        float iy0 = fmaxf(b1y0, mm.y);
        float ix1 = fmaxf(b1x1, mm.z);   // reference bug: max of maxes — replicate
        float iy1 = fmaxf(b1y1, mm.w);
        float inter = fmaxf(ix1 - ix0, 0.f) * fmaxf(iy1 - iy0, 0.f);
        float D = a1 + a2 - inter;
        return (D > 0.f) && (2.f * inter >= D);   // <=> iou >= 0.5
    };

    int n  = (int)__ldcg(&g_nvalid[LAYER * 8 + b]);
    int e0 = CELLBASE + b * CPI;
    bool hit = false;
    int j = start;
    for (; j + 3 * step < n; j += 4 * step) {     // batched -> MLP 4, L2-resident
        float4 m0 = g_boxes[e0 + j];
        float4 m1 = g_boxes[e0 + j + step];
        float4 m2 = g_boxes[e0 + j + 2 * step];
        float4 m3 = g_boxes[e0 + j + 3 * step];
        hit = hit | tst(m0) | tst(m1) | tst(m2) | tst(m3);
    }
    for (; j < n; j += step) hit = hit | tst(g_boxes[e0 + j]);
    return hit;
}

// ---------------- fused persistent kernel ----------------
__global__ void __launch_bounds__(NTH, 2) k_fused(
    const float* __restrict__ o0, const float* __restrict__ l0,
    const float* __restrict__ o1, const float* __restrict__ l1,
    const float* __restrict__ o2, const float* __restrict__ l2,
    float* __restrict__ out)
{
    const int bId  = blockIdx.x;
    const int tid  = threadIdx.x;
    const int lane = tid & 31;
    const int warp = tid >> 5;

    float s[8] = {0.f, 0.f, 0.f, 0.f, 0.f, 0.f, 0.f, 0.f};

    // ---- pass A: uniform stream ----
    if (bId < A1S)      sweep<A0N, A0S>(l0, o0, NV4_0, s, bId);
    else if (bId < A2S) sweep<A1N, A1S>(l1, o1, NV4_1, s, bId);
    else                sweep<A2N, A2S>(l2, o2, NV4_2, s, bId);

    // ---- pass B: per-cell corrections (block-aligned per layer) ----
    if (bId < BB1S) {
        int c = bId * NTH + tid;
        if (c < CELLS0) correct<0, 13, CPI0, 0>(o0, l0, c, s);
    } else if (bId < BB2S) {
        int c = (bId - BB1S) * NTH + tid;
        if (c < CELLS1) correct<1, 26, CPI1, CELLS0>(o1, l1, c, s);
    } else if (bId < BB2S + BB2N) {
        int c = (bId - BB2S) * NTH + tid;
        if (c < CELLS2) correct<2, 52, CPI2, C01>(o2, l2, c, s);
    }

    // ---- block reduce: 8 float slots -> double per-block partials ----
    __shared__ float sh[8][16];
#pragma unroll
    for (int i = 0; i < 8; i++) {
        float v = s[i];
        for (int off = 16; off; off >>= 1) v += __shfl_down_sync(FULLMASK, v, off);
        if (lane == 0) sh[i][warp] = v;
    }
    __syncthreads();
    if (tid < 8) {
        double d = 0.0;
        for (int w = 0; w < 16; w++) d += (double)sh[tid][w];
        g_part[tid][bId] = d;
    }

    // ---- grid barrier (all 296 blocks co-resident by launch_bounds) ----
    __syncthreads();
    if (tid == 0) {
        __threadfence();
        atomicAdd(&g_bar1, 1u);
        while (*(volatile unsigned int*)&g_bar1 < GRID) { }
    }
    __syncthreads();

    // ---- phase 2 (layer-2 cells split 2 threads/cell) ----
    __shared__ unsigned int shc[3];
    __shared__ bool s_last;
    if (tid < 3) shc[tid] = 0u;
    __syncthreads();

    int gtid = bId * NTH + tid;
    float obj = 1.f;           // dummy: never counts
    bool  hit = false;
    int   layer = 0;
    bool  valid = false, split = false, counter = false;
    if (gtid < CELLS0) {
        valid = true; counter = true; layer = 0;
        hit = cell_hit<0, 13, CPI0, 0>(o0, l0, gtid, 0, 1, &obj);
    } else if (gtid < C01) {
        valid = true; counter = true; layer = 1;
        hit = cell_hit<1, 26, CPI1, CELLS0>(o1, l1, gtid - CELLS0, 0, 1, &obj);
    } else {
        int u = gtid - C01;
        if (u < 2 * CELLS2) {
            valid = true; split = true; layer = 2;
            int cell = u >> 1, half = u & 1;
            counter = (half == 0);
            hit = cell_hit<2, 52, CPI2, C01>(o2, l2, cell, half, 2, &obj);
        }
    }
    // unconditional pair-combine (pairs are lane (2k,2k+1); C01 is even)
    int h  = hit ? 1 : 0;
    int hx = __shfl_xor_sync(FULLMASK, h, 1);
    bool hitc = split ? ((h | hx) != 0) : hit;
    if (valid && counter && obj == 0.f && !hitc)
        atomicAdd(&shc[layer], 1u);

    __syncthreads();
    if (tid < 3 && shc[tid]) atomicAdd(&g_cign[tid], shc[tid]);
    __syncthreads();
    if (tid == 0) {
        __threadfence();
        unsigned t = atomicAdd(&g_bar2, 1u);
        s_last = (t == (unsigned)(GRID - 1));
    }
    __syncthreads();
    if (!s_last) return;

    // ---- final reduce + combine (exactly one block, after all others finished) ----
    // slots 0,1 use pass-A block ranges; slots 2-7 use pass-B block ranges.
    __shared__ double res[3][8];
    for (int task = warp; task < 24; task += 16) {
        int layr = task >> 3, slot = task & 7;
        int start, cnt;
        if (slot < 2) {
            start = (layr == 0) ? A0S : (layr == 1) ? A1S : A2S;
            cnt   = (layr == 0) ? A0N : (layr == 1) ? A1N : A2N;
        } else {
            start = (layr == 0) ? BB0S : (layr == 1) ? BB1S : BB2S;
            cnt   = (layr == 0) ? BB0N : (layr == 1) ? BB1N : BB2N;
        }
        double d = 0.0;
        for (int i = lane; i < cnt; i += 32) d += __ldcg(&g_part[slot][start + i]);
        for (int off = 16; off; off >>= 1) d += __shfl_down_sync(FULLMASK, d, off);
        if (lane == 0) res[layr][slot] = d;
    }
    __syncthreads();
    if (tid == 0) {
        const int cpis[3] = {CPI0, CPI1, CPI2};
        double loss = 0.0;
        for (int l = 0; l < 3; l++) {
            double N     = 8.0 * (double)cpis[l];
            double U     = LN2 * res[l][0] - res[l][1];      // total bce over all 85 chans
            double scls  = U - res[l][2];                    // minus chans 0-4
            double mxy   = res[l][3] / (N * 2.0);
            double mconf = res[l][5] / N;
            double mcls  = scls / (N * 80.0);
            unsigned ci  = *(volatile unsigned int*)&g_cign[l];
            loss += mxy * res[l][6]                          // xy_loss * B
                  + res[l][4]                                // wh_loss * B
                  + mconf * (res[l][7] + (double)ci)         // conf_loss * B
                  + mcls * res[l][7];                        // class_loss * B
        }
        *out = (float)(loss / 8.0);
    }
    __syncthreads();
    // self-reset for the next graph replay (initial state is zero-init at load)
    if (tid < 24)              g_nvalid[tid] = 0u;
    if (tid >= 24 && tid < 27) g_cign[tid - 24] = 0u;
    if (tid == 30)             g_bar1 = 0u;
    if (tid == 31)             g_bar2 = 0u;
}

extern "C" void kernel_launch(void* const* d_in, const int* in_sizes, int n_in,
                              void* d_out, int out_size) {
    const float *O[3], *L[3];
    // o_i and l_i have equal element counts per layer; layers differ.
    // interleaved order (o0,l0,o1,l1,o2,l2) <=> sizes[0]==sizes[1].
    if (in_sizes[0] == in_sizes[1]) {
        O[0] = (const float*)d_in[0]; L[0] = (const float*)d_in[1];
        O[1] = (const float*)d_in[2]; L[1] = (const float*)d_in[3];
        O[2] = (const float*)d_in[4]; L[2] = (const float*)d_in[5];
    } else {
        O[0] = (const float*)d_in[0]; O[1] = (const float*)d_in[1]; O[2] = (const float*)d_in[2];
        L[0] = (const float*)d_in[3]; L[1] = (const float*)d_in[4]; L[2] = (const float*)d_in[5];
    }
    k_fused<<<GRID, NTH>>>(O[0], L[0], O[1], L[1], O[2], L[2], (float*)d_out);
}